// round 4
// baseline (speedup 1.0000x reference)
#include <cuda_runtime.h>
#include <cuda_bf16.h>

// KAN layer: y[b,o] = sum_f lerp(coeff[f, idx-1, o], coeff[f, idx, o], t) + bias[o]
// B=4096, F=128, G=64, OUT=64.  grid = linspace(-3,3,64), h=6/63, inv_h=10.5
// i = clip(ceil((x+3)*10.5), 1, 63);  t = (x+3)*10.5 - (i-1)  (unclamped)
//
// R3: the LDG gather path is capped at ~64 B/cyc/SM by within-LDG wavefront
// replays (2.07 cyc/wf). Move the gather to the smem crossbar (128 B/cyc,
// conflict-free): 16 feature-chunks x 8 features, 128 KB coeff tile per CTA,
// partial sums to __device__ scratch, tiny reduction kernel adds chunks+bias.

#define F_DIM   128
#define G_SIZE  64
#define OUT_N   64
#define FC      8                    // features per chunk
#define NCHUNK  (F_DIM / FC)         // 16
#define NB_S    9                    // sample-blocks per chunk (grid = 144)
#define TILE_S  64                   // samples per inner tile
#define THREADS 1024
#define B_TOTAL 4096
#define NTILES  (B_TOTAL / TILE_S)   // 64

#define TILE_ELEMS (FC * G_SIZE * OUT_N)          // 32768 floats = 128 KB
#define SMEM_BYTES (TILE_ELEMS * 4 + TILE_S * FC * 8)   // +sidx float2

// chunk-partial sums: [NCHUNK][B][OUT] fp32 = 16.8 MB (allowed scratch)
__device__ float g_partial[NCHUNK * B_TOTAL * OUT_N];

__global__ __launch_bounds__(THREADS, 1)
void kan_smem_kernel(const float* __restrict__ x,
                     const float* __restrict__ coeff)
{
    extern __shared__ float smem[];
    float*  tile = smem;                                   // [FC][G][OUT]
    float2* sidx = reinterpret_cast<float2*>(smem + TILE_ELEMS);  // [TILE_S][FC]

    const int tid = threadIdx.x;
    const int c   = blockIdx.x & (NCHUNK - 1);   // chunk 0..15
    const int sb  = blockIdx.x >> 4;             // sample-block 0..8

    // ---- Stage this chunk's coeff tile: 8192 float4, coalesced ----
    {
        const float4* src = reinterpret_cast<const float4*>(coeff + c * TILE_ELEMS);
        float4* dst = reinterpret_cast<float4*>(tile);
        #pragma unroll
        for (int i = 0; i < TILE_ELEMS / 4 / THREADS; ++i)
            dst[tid + i * THREADS] = src[tid + i * THREADS];
    }
    __syncthreads();

    const int s    = tid >> 4;       // local sample 0..63
    const int lane = tid & 15;
    const int o4   = lane << 2;

    for (int tileIdx = sb; tileIdx < NTILES; tileIdx += NB_S) {
        const int row0 = tileIdx * TILE_S;

        // ---- per-(sample,feature) index/t, once (512 threads) ----
        if (tid < TILE_S * FC) {
            const int ss = tid >> 3;         // 0..63
            const int ff = tid & (FC - 1);   // 0..7
            const float xv = x[(row0 + ss) * F_DIM + c * FC + ff];
            const float u  = (xv + 3.0f) * 10.5f;
            int i = (int)ceilf(u);
            i = max(1, min(i, G_SIZE - 1));
            const float t = u - (float)(i - 1);
            const int off = (ff * G_SIZE + (i - 1)) * OUT_N;  // element offset in tile
            sidx[tid] = make_float2(__int_as_float(off), t);
        }
        __syncthreads();

        // ---- gather from smem (conflict-free LDS.128) + lerp ----
        float4 acc = make_float4(0.f, 0.f, 0.f, 0.f);
        #pragma unroll
        for (int f = 0; f < FC; ++f) {
            const float2 bt = sidx[s * FC + f];       // broadcast across 16 lanes
            const float* p = tile + __float_as_int(bt.x) + o4;
            const float4 c0 = *reinterpret_cast<const float4*>(p);
            const float4 c1 = *reinterpret_cast<const float4*>(p + OUT_N);
            acc.x += c0.x + bt.y * (c1.x - c0.x);
            acc.y += c0.y + bt.y * (c1.y - c0.y);
            acc.z += c0.z + bt.y * (c1.z - c0.z);
            acc.w += c0.w + bt.y * (c1.w - c0.w);
        }

        // ---- chunk-partial to scratch (coalesced STG.128) ----
        *reinterpret_cast<float4*>(
            g_partial + ((c * B_TOTAL) + row0 + s) * OUT_N + o4) = acc;

        __syncthreads();   // protect sidx before next tile overwrites it
    }
}

// y[b,o] = bias[o] + sum_c partial[c][b][o]
__global__ __launch_bounds__(256)
void kan_reduce_kernel(const float* __restrict__ bias,
                       float* __restrict__ y)
{
    const int idx = blockIdx.x * blockDim.x + threadIdx.x;  // float4 id, 65536 total
    const int o4  = (idx & 15) << 2;

    float4 acc = *reinterpret_cast<const float4*>(bias + o4);
    const float4* p = reinterpret_cast<const float4*>(g_partial) + idx;

    #pragma unroll
    for (int c = 0; c < NCHUNK; ++c) {
        const float4 v = p[c * (B_TOTAL * OUT_N / 4)];
        acc.x += v.x; acc.y += v.y; acc.z += v.z; acc.w += v.w;
    }
    reinterpret_cast<float4*>(y)[idx] = acc;
}

extern "C" void kernel_launch(void* const* d_in, const int* in_sizes, int n_in,
                              void* d_out, int out_size)
{
    const float* x     = (const float*)d_in[0];   // [4096, 128]
    const float* coeff = (const float*)d_in[1];   // [128, 64, 64]
    const float* bias  = (const float*)d_in[2];   // [64]
    float* y           = (float*)d_out;           // [4096, 64]

    cudaFuncSetAttribute(kan_smem_kernel,
                         cudaFuncAttributeMaxDynamicSharedMemorySize, SMEM_BYTES);

    kan_smem_kernel<<<NCHUNK * NB_S, THREADS, SMEM_BYTES>>>(x, coeff);
    kan_reduce_kernel<<<B_TOTAL * OUT_N / 4 / 256, 256>>>(bias, y);
}

// round 5
// speedup vs baseline: 1.2251x; 1.2251x over previous
#include <cuda_runtime.h>
#include <cuda_bf16.h>

// KAN layer: y[b,o] = sum_f lerp(coeff[f, i-1, o], coeff[f, i, o], t) + bias[o]
// B=4096, F=128, G=64, OUT=64.  i = clip(ceil((x+3)*10.5), 1, 63); t = (x+3)*10.5-(i-1)
//
// R4: chunked smem gather (16 chunks x 8 features, 128KB tile/CTA) like R3, but:
//  - ALL index/t pairs for the CTA precomputed in one phase -> ONE barrier total,
//    gather loop is barrier-free (R3 paid 2 barriers + idx latency per tile x7).
//  - sample assignment round-robin mod 9 (balance +-1 sample, not +-1 tile).
//  - reduce kernel: 1 thread per output scalar, 16 independent loads (was 7.6us
//    at occ 21% / issue 4.7%; now full occupancy, MLP=16).

#define F_DIM   128
#define G_SIZE  64
#define OUT_N   64
#define FC      8
#define NCHUNK  (F_DIM / FC)      // 16
#define NB_S    9                 // sample-blocks per chunk -> grid 144
#define THREADS 1024
#define B_TOTAL 4096
#define MAX_S   456               // ceil(4096/9)

#define TILE_ELEMS (FC * G_SIZE * OUT_N)              // 32768 floats = 128 KB
#define SIDX_ELEMS (MAX_S * FC)                       // 3648 float2 = 29184 B
#define SMEM_BYTES (TILE_ELEMS * 4 + SIDX_ELEMS * 8)  // 160256 B

__device__ float g_partial[NCHUNK * B_TOTAL * OUT_N];  // 16.8 MB scratch

__global__ __launch_bounds__(THREADS, 1)
void kan_smem_kernel(const float* __restrict__ x,
                     const float* __restrict__ coeff)
{
    extern __shared__ float smem[];
    float*  tile = smem;                                          // [FC][G][OUT]
    float2* sidx = reinterpret_cast<float2*>(smem + TILE_ELEMS);  // [MAX_S][FC]

    const int tid = threadIdx.x;
    const int c   = blockIdx.x & (NCHUNK - 1);   // chunk 0..15
    const int sb  = blockIdx.x >> 4;             // sample-phase 0..8
    const int nS  = (B_TOTAL - sb + NB_S - 1) / NB_S;   // samples for this CTA

    // ---- Stage coeff chunk: 8192 float4, coalesced ----
    {
        const float4* src = reinterpret_cast<const float4*>(coeff + c * TILE_ELEMS);
        float4* dst = reinterpret_cast<float4*>(tile);
        #pragma unroll
        for (int i = 0; i < TILE_ELEMS / 4 / THREADS; ++i)
            dst[tid + i * THREADS] = src[tid + i * THREADS];
    }

    // ---- Index phase: ALL (sample, feature) pairs for this CTA, once ----
    {
        const int nPairs = nS * FC;
        for (int p = tid; p < nPairs; p += THREADS) {
            const int sl = p >> 3;           // local sample
            const int ff = p & (FC - 1);
            const int b  = sb + sl * NB_S;   // global sample
            const float xv = x[b * F_DIM + c * FC + ff];
            const float u  = (xv + 3.0f) * 10.5f;
            int i = (int)ceilf(u);
            i = max(1, min(i, G_SIZE - 1));
            const float t = u - (float)(i - 1);
            const int off = (ff * G_SIZE + (i - 1)) * OUT_N;
            sidx[p] = make_float2(__int_as_float(off), t);
        }
    }
    __syncthreads();   // the ONLY barrier

    // ---- Gather: warp = 2 samples x 16 lanes, loop stride 64 samples ----
    const int lane16 = tid & 15;
    const int o4     = lane16 << 2;
    const int my_s   = ((tid >> 5) << 1) + ((tid >> 4) & 1);  // 0..63

    const float* cb = tile + o4;

    for (int s = my_s; s < nS; s += 64) {
        const float2* sp = sidx + s * FC;
        float4 acc = make_float4(0.f, 0.f, 0.f, 0.f);

        #pragma unroll
        for (int f = 0; f < FC; ++f) {
            const float2 bt = sp[f];                 // broadcast over 16 lanes
            const float* p = cb + __float_as_int(bt.x);
            const float4 c0 = *reinterpret_cast<const float4*>(p);
            const float4 c1 = *reinterpret_cast<const float4*>(p + OUT_N);
            acc.x += c0.x + bt.y * (c1.x - c0.x);
            acc.y += c0.y + bt.y * (c1.y - c0.y);
            acc.z += c0.z + bt.y * (c1.z - c0.z);
            acc.w += c0.w + bt.y * (c1.w - c0.w);
        }

        const int b = sb + s * NB_S;
        *reinterpret_cast<float4*>(
            g_partial + ((c * B_TOTAL) + b) * OUT_N + o4) = acc;
    }
}

// y[e] = bias[e&63] + sum_c partial[c*B*OUT + e], one thread per scalar
__global__ __launch_bounds__(256)
void kan_reduce_kernel(const float* __restrict__ bias,
                       float* __restrict__ y)
{
    const int e = blockIdx.x * 256 + threadIdx.x;   // 0..262143
    const int o = e & (OUT_N - 1);

    float acc = __ldg(bias + o);
    const float* p = g_partial + e;

    #pragma unroll
    for (int c = 0; c < NCHUNK; ++c)
        acc += p[c * (B_TOTAL * OUT_N)];

    y[e] = acc;
}

extern "C" void kernel_launch(void* const* d_in, const int* in_sizes, int n_in,
                              void* d_out, int out_size)
{
    const float* x     = (const float*)d_in[0];   // [4096, 128]
    const float* coeff = (const float*)d_in[1];   // [128, 64, 64]
    const float* bias  = (const float*)d_in[2];   // [64]
    float* y           = (float*)d_out;           // [4096, 64]

    static int configured = 0;
    if (!configured) {
        cudaFuncSetAttribute(kan_smem_kernel,
                             cudaFuncAttributeMaxDynamicSharedMemorySize, SMEM_BYTES);
        configured = 1;
    }

    kan_smem_kernel<<<NCHUNK * NB_S, THREADS, SMEM_BYTES>>>(x, coeff);
    kan_reduce_kernel<<<B_TOTAL * OUT_N / 256, 256>>>(bias, y);
}